// round 1
// baseline (speedup 1.0000x reference)
#include <cuda_runtime.h>
#include <math.h>

// Problem constants (fixed by the dataset)
#define NN    50000
#define FDIM  160
#define G4    640
#define DEG   16
#define OUTC  128

// Scratch (device globals — no runtime allocation allowed)
__device__ float g_hin [(size_t)NN * FDIM];   // concat(x, emb)           32 MB
__device__ float g_gall[(size_t)NN * G4];     // h_in@W_ih^T + b_ih+b_hh 128 MB
__device__ float g_rout[(size_t)NN * OUTC];   // h_in@W_r^T + b_l         25.6 MB
__device__ float g_wt  [FDIM * G4];           // W_hh transposed [k][row] 400 KB
__device__ float g_bias[G4];                  // b_ih + b_hh

// ---------------------------------------------------------------------------
// Kernel 1: h_in = concat(x, emb_table[node_type_ids])   (float4 granularity)
// ---------------------------------------------------------------------------
__global__ void concat_kernel(const float* __restrict__ x,
                              const int* __restrict__ types,
                              const float* __restrict__ emb, int N) {
    int i = blockIdx.x * blockDim.x + threadIdx.x;   // float4 index over N*40
    if (i >= N * 40) return;
    int n = i / 40;
    int q = i - n * 40;
    float4 v;
    if (q < 32) {
        v = ((const float4*)x)[n * 32 + q];
    } else {
        int tp = types[n];
        v = ((const float4*)emb)[tp * 8 + (q - 32)];
    }
    ((float4*)g_hin)[i] = v;
}

// ---------------------------------------------------------------------------
// Kernel 2: combined bias + W_hh transpose to k-major
// ---------------------------------------------------------------------------
__global__ void prep_kernel(const float* __restrict__ W_hh,
                            const float* __restrict__ b_ih,
                            const float* __restrict__ b_hh) {
    int t0 = blockIdx.x * blockDim.x + threadIdx.x;
    if (t0 < G4) g_bias[t0] = b_ih[t0] + b_hh[t0];
    int total = G4 * FDIM;
    int stride = gridDim.x * blockDim.x;
    for (int idx = t0; idx < total; idx += stride) {
        int r = idx / FDIM;
        int k = idx - r * FDIM;
        g_wt[k * G4 + r] = W_hh[idx];
    }
}

// ---------------------------------------------------------------------------
// Kernel 3: generic C[M,Nc] = h_in[M,160] @ B[Nc,160]^T + bias
//   mode 0: C = g_gall (Nc=640), bias = g_bias
//   mode 1: C = g_rout (Nc=128), bias = biasp (b_l)
// BM=BN=64, BK=16, 256 threads, 4x4 register tile.
// ---------------------------------------------------------------------------
__global__ void gemm_kernel(const float* __restrict__ B,
                            const float* __restrict__ biasp,
                            int Nc, int N, int mode) {
    __shared__ float As[16][64];
    __shared__ float Bs[16][64];
    const float* A = g_hin;
    float* C = (mode == 0) ? g_gall : g_rout;

    int m0 = blockIdx.y * 64;
    int n0 = blockIdx.x * 64;
    int t  = threadIdx.x;
    int lr = t >> 2, lq = t & 3;     // load mapping: 64 rows x 4 float4
    int tx = t & 15, ty = t >> 4;    // compute mapping: 16x16 threads

    float acc[4][4];
#pragma unroll
    for (int i = 0; i < 4; i++)
#pragma unroll
        for (int j = 0; j < 4; j++) acc[i][j] = 0.f;

    for (int kc = 0; kc < FDIM; kc += 16) {
        float4 av = make_float4(0.f, 0.f, 0.f, 0.f);
        int am = m0 + lr;
        if (am < N) av = *(const float4*)(A + (size_t)am * FDIM + kc + lq * 4);
        As[lq * 4 + 0][lr] = av.x; As[lq * 4 + 1][lr] = av.y;
        As[lq * 4 + 2][lr] = av.z; As[lq * 4 + 3][lr] = av.w;

        float4 bv = *(const float4*)(B + (size_t)(n0 + lr) * FDIM + kc + lq * 4);
        Bs[lq * 4 + 0][lr] = bv.x; Bs[lq * 4 + 1][lr] = bv.y;
        Bs[lq * 4 + 2][lr] = bv.z; Bs[lq * 4 + 3][lr] = bv.w;
        __syncthreads();

#pragma unroll
        for (int kk = 0; kk < 16; kk++) {
            float4 a4 = *(const float4*)&As[kk][ty * 4];
            float4 b4 = *(const float4*)&Bs[kk][tx * 4];
            float a[4] = {a4.x, a4.y, a4.z, a4.w};
            float b[4] = {b4.x, b4.y, b4.z, b4.w};
#pragma unroll
            for (int i = 0; i < 4; i++)
#pragma unroll
                for (int j = 0; j < 4; j++) acc[i][j] += a[i] * b[j];
        }
        __syncthreads();
    }

    const float* bias = (mode == 0) ? g_bias : biasp;
    float4 bb = *(const float4*)(bias + n0 + tx * 4);
    float bj[4] = {bb.x, bb.y, bb.z, bb.w};
#pragma unroll
    for (int i = 0; i < 4; i++) {
        int m = m0 + ty * 4 + i;
        if (m < N) {
            float4 o;
            o.x = acc[i][0] + bj[0];
            o.y = acc[i][1] + bj[1];
            o.z = acc[i][2] + bj[2];
            o.w = acc[i][3] + bj[3];
            *(float4*)(C + (size_t)m * Nc + n0 + tx * 4) = o;
        }
    }
}

// ---------------------------------------------------------------------------
// Kernel 4: persistent-tile LSTM over 16 neighbors + fused SAGE projection.
// CTA = 320 threads, 32 nodes. Thread tile: 4 nodes x 4 hidden x 4 gates (64 acc).
// h in SMEM, c in registers, W_hh streamed k-major via SMEM with reg prefetch.
// ---------------------------------------------------------------------------
__device__ __forceinline__ float sigm(float x)     { return 1.f / (1.f + __expf(-x)); }
__device__ __forceinline__ float tanhfast(float x) { return 1.f - 2.f / (1.f + __expf(2.f * x)); }

__global__ __launch_bounds__(320) void lstm_kernel(const int* __restrict__ src,
                                                   const float* __restrict__ Wl,
                                                   float* __restrict__ out, int N) {
    __shared__ float sh_h[32][168];     // padded rows (bank shift), 21.5 KB
    __shared__ float sh_w[8 * 640];     // one k-chunk of W_hh^T, 20 KB

    int t  = threadIdx.x;
    int mg = t / 40;            // 0..7  -> node group
    int rg = t % 40;            // 0..39 -> hidden group
    int mbase = mg * 4;
    int r0 = rg * 4;
    int node0 = blockIdx.x * 32;

    // zero-init h (pad included — harmless)
    for (int i = t; i < 32 * 168; i += 320) (&sh_h[0][0])[i] = 0.f;

    float cst[4][4];
#pragma unroll
    for (int i = 0; i < 4; i++)
#pragma unroll
        for (int j = 0; j < 4; j++) cst[i][j] = 0.f;

    // preload W chunk 0 into registers
    float4 wbuf[4];
    {
        const float4* ws = (const float4*)g_wt;
#pragma unroll
        for (int q = 0; q < 4; q++) wbuf[q] = ws[q * 320 + t];
    }
    __syncthreads();

    for (int step = 0; step < DEG; step++) {
        // accumulator init = gathered precomputed input gates (incl. biases)
        float acc[4][16];
#pragma unroll
        for (int mi = 0; mi < 4; mi++) {
            int nd = node0 + mbase + mi;
            int s = (nd < N) ? src[nd * DEG + step] : 0;
            const float4* gp = (const float4*)(g_gall + (size_t)s * G4);
#pragma unroll
            for (int gi = 0; gi < 4; gi++) {
                float4 v = gp[gi * 40 + rg];
                acc[mi][gi * 4 + 0] = v.x; acc[mi][gi * 4 + 1] = v.y;
                acc[mi][gi * 4 + 2] = v.z; acc[mi][gi * 4 + 3] = v.w;
            }
        }

        // recurrent GEMM: acc += h @ W_hh^T   (k-chunks of 8, reg-staged prefetch)
        for (int kc = 0; kc < FDIM; kc += 8) {
            __syncthreads();                       // prior chunk reads done
            float4* wd = (float4*)sh_w;
#pragma unroll
            for (int q = 0; q < 4; q++) wd[q * 320 + t] = wbuf[q];
            __syncthreads();
            {   // prefetch next chunk (chunk 0 of next step when wrapping)
                int nk = (kc + 8 < FDIM) ? kc + 8 : 0;
                const float4* ws = (const float4*)(g_wt + nk * G4);
#pragma unroll
                for (int q = 0; q < 4; q++) wbuf[q] = ws[q * 320 + t];
            }
#pragma unroll
            for (int kk = 0; kk < 8; kk++) {
                float a[4];
#pragma unroll
                for (int mi = 0; mi < 4; mi++) a[mi] = sh_h[mbase + mi][kc + kk];
#pragma unroll
                for (int gi = 0; gi < 4; gi++) {
                    float4 b = *(const float4*)&sh_w[kk * 640 + gi * 160 + r0];
#pragma unroll
                    for (int mi = 0; mi < 4; mi++) {
                        acc[mi][gi * 4 + 0] += a[mi] * b.x;
                        acc[mi][gi * 4 + 1] += a[mi] * b.y;
                        acc[mi][gi * 4 + 2] += a[mi] * b.z;
                        acc[mi][gi * 4 + 3] += a[mi] * b.w;
                    }
                }
            }
        }
        __syncthreads();   // all sh_h reads done before update

        // elementwise LSTM cell update; write new h to SMEM
#pragma unroll
        for (int mi = 0; mi < 4; mi++) {
            float hnew[4];
#pragma unroll
            for (int j = 0; j < 4; j++) {
                float ig = acc[mi][0 + j];
                float fg = acc[mi][4 + j];
                float gg = acc[mi][8 + j];
                float og = acc[mi][12 + j];
                float cn = sigm(fg) * cst[mi][j] + sigm(ig) * tanhfast(gg);
                cst[mi][j] = cn;
                hnew[j] = sigm(og) * tanhfast(cn);
            }
            *(float4*)&sh_h[mbase + mi][r0] =
                make_float4(hnew[0], hnew[1], hnew[2], hnew[3]);
        }
        __syncthreads();
    }

    // fused SAGE projection: out = relu(h_last @ W_l^T + (h_in @ W_r^T + b_l))
    if (rg < 32) {
        int c0 = rg * 4;   // output column 0..124
#pragma unroll
        for (int mi = 0; mi < 4; mi++) {
            int m = mbase + mi;
            int nd = node0 + m;
            if (nd >= N) continue;
            float s0 = 0.f, s1 = 0.f, s2 = 0.f, s3 = 0.f;
#pragma unroll 4
            for (int k = 0; k < FDIM; k += 4) {
                float4 hv = *(const float4*)&sh_h[m][k];
                float4 w0 = *(const float4*)(Wl + (size_t)(c0 + 0) * FDIM + k);
                float4 w1 = *(const float4*)(Wl + (size_t)(c0 + 1) * FDIM + k);
                float4 w2 = *(const float4*)(Wl + (size_t)(c0 + 2) * FDIM + k);
                float4 w3 = *(const float4*)(Wl + (size_t)(c0 + 3) * FDIM + k);
                s0 += hv.x * w0.x + hv.y * w0.y + hv.z * w0.z + hv.w * w0.w;
                s1 += hv.x * w1.x + hv.y * w1.y + hv.z * w1.z + hv.w * w1.w;
                s2 += hv.x * w2.x + hv.y * w2.y + hv.z * w2.z + hv.w * w2.w;
                s3 += hv.x * w3.x + hv.y * w3.y + hv.z * w3.z + hv.w * w3.w;
            }
            float4 rv = *(const float4*)(g_rout + (size_t)nd * OUTC + c0);
            float4 o;
            o.x = fmaxf(s0 + rv.x, 0.f);
            o.y = fmaxf(s1 + rv.y, 0.f);
            o.z = fmaxf(s2 + rv.z, 0.f);
            o.w = fmaxf(s3 + rv.w, 0.f);
            *(float4*)(out + (size_t)nd * OUTC + c0) = o;
        }
    }
}

// ---------------------------------------------------------------------------
// Launcher (graph-capturable: kernel launches only, stream-ordered deps)
// ---------------------------------------------------------------------------
extern "C" void kernel_launch(void* const* d_in, const int* in_sizes, int n_in,
                              void* d_out, int out_size) {
    const float* x     = (const float*)d_in[0];
    const int*   types = (const int*)d_in[1];
    const int*   eidx  = (const int*)d_in[2];   // [2, E]: first E entries = src
    const float* emb   = (const float*)d_in[3];
    const float* W_ih  = (const float*)d_in[4];
    const float* W_hh  = (const float*)d_in[5];
    const float* b_ih  = (const float*)d_in[6];
    const float* b_hh  = (const float*)d_in[7];
    const float* W_l   = (const float*)d_in[8];
    const float* b_l   = (const float*)d_in[9];
    const float* W_r   = (const float*)d_in[10];
    float* out = (float*)d_out;

    int N = in_sizes[1];                 // = 50000
    const int* srcp = eidx;              // src row of edge_index

    concat_kernel<<<(N * 40 + 255) / 256, 256>>>(x, types, emb, N);
    prep_kernel<<<160, 256>>>(W_hh, b_ih, b_hh);

    dim3 g1(G4 / 64, (N + 63) / 64);
    gemm_kernel<<<g1, 256>>>(W_ih, nullptr, G4, N, 0);
    dim3 g2(OUTC / 64, (N + 63) / 64);
    gemm_kernel<<<g2, 256>>>(W_r, b_l, OUTC, N, 1);

    lstm_kernel<<<(N + 31) / 32, 320>>>(srcp, W_l, out, N);
}

// round 5
// speedup vs baseline: 1.1770x; 1.1770x over previous
#include <cuda_runtime.h>
#include <math.h>

// Problem constants (fixed by the dataset)
#define NN    50000
#define FDIM  160
#define G4    640
#define DEG   16
#define OUTC  128

typedef unsigned long long ull;

// Scratch (device globals — no runtime allocation allowed)
__device__ float g_hin [(size_t)NN * FDIM];   // concat(x, emb)           32 MB
__device__ float g_gall[(size_t)NN * G4];     // h_in@W_ih^T + b_ih+b_hh 128 MB
__device__ float g_rout[(size_t)NN * OUTC];   // h_in@W_r^T + b_l         25.6 MB
__device__ float g_wt  [FDIM * G4];           // W_hh transposed [k][row] 400 KB
__device__ float g_bias[G4];                  // b_ih + b_hh

// ---------------------------------------------------------------------------
// packed fp32x2 helpers (SASS FFMA2 — 2 full-precision fp32 FMAs / instr)
// ---------------------------------------------------------------------------
__device__ __forceinline__ ull ffma2(ull a, ull b, ull c) {
    ull d;
    asm("fma.rn.f32x2 %0, %1, %2, %3;" : "=l"(d) : "l"(a), "l"(b), "l"(c));
    return d;
}
__device__ __forceinline__ ull dup2(float x) {
    ull r; asm("mov.b64 %0, {%1, %1};" : "=l"(r) : "f"(x)); return r;
}
__device__ __forceinline__ float2 unpk(ull v) {
    float2 r; asm("mov.b64 {%0, %1}, %2;" : "=f"(r.x), "=f"(r.y) : "l"(v)); return r;
}

// ---------------------------------------------------------------------------
// Kernel 1: h_in = concat(x, emb_table[node_type_ids])   (float4 granularity)
// ---------------------------------------------------------------------------
__global__ void concat_kernel(const float* __restrict__ x,
                              const int* __restrict__ types,
                              const float* __restrict__ emb, int N) {
    int i = blockIdx.x * blockDim.x + threadIdx.x;   // float4 index over N*40
    if (i >= N * 40) return;
    int n = i / 40;
    int q = i - n * 40;
    float4 v;
    if (q < 32) {
        v = ((const float4*)x)[n * 32 + q];
    } else {
        int tp = types[n];
        v = ((const float4*)emb)[tp * 8 + (q - 32)];
    }
    ((float4*)g_hin)[i] = v;
}

// ---------------------------------------------------------------------------
// Kernel 2: combined bias + W_hh transpose to k-major
// ---------------------------------------------------------------------------
__global__ void prep_kernel(const float* __restrict__ W_hh,
                            const float* __restrict__ b_ih,
                            const float* __restrict__ b_hh) {
    int t0 = blockIdx.x * blockDim.x + threadIdx.x;
    if (t0 < G4) g_bias[t0] = b_ih[t0] + b_hh[t0];
    int total = G4 * FDIM;
    int stride = gridDim.x * blockDim.x;
    for (int idx = t0; idx < total; idx += stride) {
        int r = idx / FDIM;
        int k = idx - r * FDIM;
        g_wt[k * G4 + r] = W_hh[idx];
    }
}

// ---------------------------------------------------------------------------
// Kernel 3: generic C[M,Nc] = h_in[M,160] @ B[Nc,160]^T + bias   (FFMA2)
//   mode 0: C = g_gall (Nc=640), bias = g_bias
//   mode 1: C = g_rout (Nc=128), bias = biasp (b_l)
// BM=BN=64, BK=16, 256 threads, 4x4 register tile as 4x2 packed pairs.
// ---------------------------------------------------------------------------
__global__ void gemm_kernel(const float* __restrict__ B,
                            const float* __restrict__ biasp,
                            int Nc, int N, int mode) {
    __shared__ float As[16][64];
    __shared__ float Bs[16][64];
    const float* A = g_hin;
    float* C = (mode == 0) ? g_gall : g_rout;

    int m0 = blockIdx.y * 64;
    int n0 = blockIdx.x * 64;
    int t  = threadIdx.x;
    int lr = t >> 2, lq = t & 3;     // load mapping: 64 rows x 4 float4
    int tx = t & 15, ty = t >> 4;    // compute mapping: 16x16 threads

    ull acc[4][2];
#pragma unroll
    for (int i = 0; i < 4; i++) { acc[i][0] = 0ull; acc[i][1] = 0ull; }

    for (int kc = 0; kc < FDIM; kc += 16) {
        float4 av = make_float4(0.f, 0.f, 0.f, 0.f);
        int am = m0 + lr;
        if (am < N) av = *(const float4*)(A + (size_t)am * FDIM + kc + lq * 4);
        As[lq * 4 + 0][lr] = av.x; As[lq * 4 + 1][lr] = av.y;
        As[lq * 4 + 2][lr] = av.z; As[lq * 4 + 3][lr] = av.w;

        float4 bv = *(const float4*)(B + (size_t)(n0 + lr) * FDIM + kc + lq * 4);
        Bs[lq * 4 + 0][lr] = bv.x; Bs[lq * 4 + 1][lr] = bv.y;
        Bs[lq * 4 + 2][lr] = bv.z; Bs[lq * 4 + 3][lr] = bv.w;
        __syncthreads();

#pragma unroll
        for (int kk = 0; kk < 16; kk++) {
            float4 a4 = *(const float4*)&As[kk][ty * 4];
            longlong2 b2 = *(const longlong2*)&Bs[kk][tx * 4];
            ull bx = (ull)b2.x, by = (ull)b2.y;
            float a[4] = {a4.x, a4.y, a4.z, a4.w};
#pragma unroll
            for (int i = 0; i < 4; i++) {
                ull a2 = dup2(a[i]);
                acc[i][0] = ffma2(a2, bx, acc[i][0]);
                acc[i][1] = ffma2(a2, by, acc[i][1]);
            }
        }
        __syncthreads();
    }

    const float* bias = (mode == 0) ? g_bias : biasp;
    float4 bb = *(const float4*)(bias + n0 + tx * 4);
#pragma unroll
    for (int i = 0; i < 4; i++) {
        int m = m0 + ty * 4 + i;
        if (m < N) {
            float2 lo = unpk(acc[i][0]);
            float2 hi = unpk(acc[i][1]);
            float4 o;
            o.x = lo.x + bb.x;
            o.y = lo.y + bb.y;
            o.z = hi.x + bb.z;
            o.w = hi.y + bb.w;
            *(float4*)(C + (size_t)m * Nc + n0 + tx * 4) = o;
        }
    }
}

// ---------------------------------------------------------------------------
// Kernel 4: persistent-tile LSTM over 16 neighbors + fused SAGE projection.
// CTA = 320 threads, 32 nodes. Thread tile: 8 nodes x 2 hidden x 4 gates
// kept as 32 packed f32x2 accumulators -> FFMA2-pipe-bound.
// h in SMEM, c in registers, W_hh streamed k-major via SMEM with reg prefetch.
// ---------------------------------------------------------------------------
__device__ __forceinline__ float sigm(float x)     { return 1.f / (1.f + __expf(-x)); }
__device__ __forceinline__ float tanhfast(float x) { return 1.f - 2.f / (1.f + __expf(2.f * x)); }

__global__ __launch_bounds__(320) void lstm_kernel(const int* __restrict__ src,
                                                   const float* __restrict__ Wl,
                                                   float* __restrict__ out, int N) {
    __shared__ float sh_h[32][168];     // padded rows, 21.5 KB
    __shared__ float sh_w[8 * 640];     // one k-chunk of W_hh^T, 20 KB

    int t  = threadIdx.x;
    int mg = t / 80;            // 0..3  -> node group (8 nodes each)
    int rg = t % 80;            // 0..79 -> hidden pair index (2 floats)
    int mbase = mg * 8;
    int node0 = blockIdx.x * 32;

    // zero-init h (pad included — harmless)
    for (int i = t; i < 32 * 168; i += 320) (&sh_h[0][0])[i] = 0.f;

    float cst[8][2];
#pragma unroll
    for (int i = 0; i < 8; i++) { cst[i][0] = 0.f; cst[i][1] = 0.f; }

    // preload W chunk 0 into registers
    float4 wbuf[4];
    {
        const float4* ws = (const float4*)g_wt;
#pragma unroll
        for (int q = 0; q < 4; q++) wbuf[q] = ws[q * 320 + t];
    }
    __syncthreads();

    for (int step = 0; step < DEG; step++) {
        // accumulator init = gathered precomputed input gates (incl. biases)
        // acc[mi][gi] holds gate block gi, hidden pair rg, for node mbase+mi
        ull acc[8][4];
#pragma unroll
        for (int mi = 0; mi < 8; mi++) {
            int nd = node0 + mbase + mi;
            int s = (nd < N) ? src[nd * DEG + step] : 0;
            const ull* gp = (const ull*)(g_gall + (size_t)s * G4);
#pragma unroll
            for (int gi = 0; gi < 4; gi++) acc[mi][gi] = gp[gi * 80 + rg];
        }

        // recurrent GEMM: acc += h @ W_hh^T   (k-chunks of 8, reg-staged prefetch)
        for (int kc = 0; kc < FDIM; kc += 8) {
            __syncthreads();                       // prior chunk reads done
            float4* wd = (float4*)sh_w;
#pragma unroll
            for (int q = 0; q < 4; q++) wd[q * 320 + t] = wbuf[q];
            __syncthreads();
            {   // prefetch next chunk (chunk 0 of next step when wrapping)
                int nk = (kc + 8 < FDIM) ? kc + 8 : 0;
                const float4* ws = (const float4*)(g_wt + nk * G4);
#pragma unroll
                for (int q = 0; q < 4; q++) wbuf[q] = ws[q * 320 + t];
            }
#pragma unroll
            for (int kk = 0; kk < 8; kk++) {
                ull b[4];
#pragma unroll
                for (int gi = 0; gi < 4; gi++)
                    b[gi] = *(const ull*)&sh_w[kk * 640 + gi * 160 + rg * 2];
#pragma unroll
                for (int mi = 0; mi < 8; mi++) {
                    ull a2 = dup2(sh_h[mbase + mi][kc + kk]);   // smem broadcast
#pragma unroll
                    for (int gi = 0; gi < 4; gi++)
                        acc[mi][gi] = ffma2(a2, b[gi], acc[mi][gi]);
                }
            }
        }
        __syncthreads();   // all sh_h reads done before update

        // elementwise LSTM cell update; write new h pair to SMEM
#pragma unroll
        for (int mi = 0; mi < 8; mi++) {
            float2 ig = unpk(acc[mi][0]);
            float2 fg = unpk(acc[mi][1]);
            float2 gg = unpk(acc[mi][2]);
            float2 og = unpk(acc[mi][3]);
            float c0 = sigm(fg.x) * cst[mi][0] + sigm(ig.x) * tanhfast(gg.x);
            float c1 = sigm(fg.y) * cst[mi][1] + sigm(ig.y) * tanhfast(gg.y);
            cst[mi][0] = c0; cst[mi][1] = c1;
            float2 hn;
            hn.x = sigm(og.x) * tanhfast(c0);
            hn.y = sigm(og.y) * tanhfast(c1);
            *(float2*)&sh_h[mbase + mi][rg * 2] = hn;
        }
        __syncthreads();
    }

    // fused SAGE projection: out = relu(h_last @ W_l^T + (h_in @ W_r^T + b_l))
    if (rg < 64) {
        int c0 = rg * 2;            // output columns c0, c0+1
        float s[8][2];
#pragma unroll
        for (int mi = 0; mi < 8; mi++) { s[mi][0] = 0.f; s[mi][1] = 0.f; }
#pragma unroll 4
        for (int k = 0; k < FDIM; k += 4) {
            float4 w0 = *(const float4*)(Wl + (size_t)(c0 + 0) * FDIM + k);
            float4 w1 = *(const float4*)(Wl + (size_t)(c0 + 1) * FDIM + k);
#pragma unroll
            for (int mi = 0; mi < 8; mi++) {
                float4 hv = *(const float4*)&sh_h[mbase + mi][k];
                s[mi][0] += hv.x * w0.x + hv.y * w0.y + hv.z * w0.z + hv.w * w0.w;
                s[mi][1] += hv.x * w1.x + hv.y * w1.y + hv.z * w1.z + hv.w * w1.w;
            }
        }
#pragma unroll
        for (int mi = 0; mi < 8; mi++) {
            int nd = node0 + mbase + mi;
            if (nd >= N) continue;
            float2 rv = *(const float2*)(g_rout + (size_t)nd * OUTC + c0);
            float2 o;
            o.x = fmaxf(s[mi][0] + rv.x, 0.f);
            o.y = fmaxf(s[mi][1] + rv.y, 0.f);
            *(float2*)(out + (size_t)nd * OUTC + c0) = o;
        }
    }
}

// ---------------------------------------------------------------------------
// Launcher (graph-capturable: kernel launches only, stream-ordered deps)
// ---------------------------------------------------------------------------
extern "C" void kernel_launch(void* const* d_in, const int* in_sizes, int n_in,
                              void* d_out, int out_size) {
    const float* x     = (const float*)d_in[0];
    const int*   types = (const int*)d_in[1];
    const int*   eidx  = (const int*)d_in[2];   // [2, E]: first E entries = src
    const float* emb   = (const float*)d_in[3];
    const float* W_ih  = (const float*)d_in[4];
    const float* W_hh  = (const float*)d_in[5];
    const float* b_ih  = (const float*)d_in[6];
    const float* b_hh  = (const float*)d_in[7];
    const float* W_l   = (const float*)d_in[8];
    const float* b_l   = (const float*)d_in[9];
    const float* W_r   = (const float*)d_in[10];
    float* out = (float*)d_out;

    int N = in_sizes[1];                 // = 50000
    const int* srcp = eidx;              // src row of edge_index

    concat_kernel<<<(N * 40 + 255) / 256, 256>>>(x, types, emb, N);
    prep_kernel<<<160, 256>>>(W_hh, b_ih, b_hh);

    dim3 g1(G4 / 64, (N + 63) / 64);
    gemm_kernel<<<g1, 256>>>(W_ih, nullptr, G4, N, 0);
    dim3 g2(OUTC / 64, (N + 63) / 64);
    gemm_kernel<<<g2, 256>>>(W_r, b_l, OUTC, N, 1);

    lstm_kernel<<<(N + 31) / 32, 320>>>(srcp, W_l, out, N);
}

// round 6
// speedup vs baseline: 1.1779x; 1.0008x over previous
#include <cuda_runtime.h>
#include <math.h>

// Problem constants (fixed by the dataset)
#define NN    50000
#define FDIM  160
#define G4    640
#define DEG   16
#define OUTC  128

typedef unsigned long long ull;

// Scratch (device globals — no runtime allocation allowed)
__device__ float g_hin [(size_t)NN * FDIM];   // concat(x, emb)           32 MB
__device__ float g_gall[(size_t)NN * G4];     // h_in@W_ih^T + b_ih+b_hh 128 MB
__device__ float g_rout[(size_t)NN * OUTC];   // h_in@W_r^T + b_l         25.6 MB
__device__ float g_wt  [FDIM * G4];           // W_hh transposed [k][row] 400 KB
__device__ float g_bias[G4];                  // b_ih + b_hh

// ---------------------------------------------------------------------------
// packed fp32x2 helpers (SASS FFMA2 — 2 full-precision fp32 FMAs / instr)
// ---------------------------------------------------------------------------
__device__ __forceinline__ ull ffma2(ull a, ull b, ull c) {
    ull d;
    asm("fma.rn.f32x2 %0, %1, %2, %3;" : "=l"(d) : "l"(a), "l"(b), "l"(c));
    return d;
}
__device__ __forceinline__ ull dup2(float x) {
    ull r; asm("mov.b64 %0, {%1, %1};" : "=l"(r) : "f"(x)); return r;
}
__device__ __forceinline__ float2 unpk(ull v) {
    float2 r; asm("mov.b64 {%0, %1}, %2;" : "=f"(r.x), "=f"(r.y) : "l"(v)); return r;
}

// ---------------------------------------------------------------------------
// Kernel 1: h_in = concat(x, emb_table[node_type_ids])   (float4 granularity)
// ---------------------------------------------------------------------------
__global__ void concat_kernel(const float* __restrict__ x,
                              const int* __restrict__ types,
                              const float* __restrict__ emb, int N) {
    int i = blockIdx.x * blockDim.x + threadIdx.x;   // float4 index over N*40
    if (i >= N * 40) return;
    int n = i / 40;
    int q = i - n * 40;
    float4 v;
    if (q < 32) {
        v = ((const float4*)x)[n * 32 + q];
    } else {
        int tp = types[n];
        v = ((const float4*)emb)[tp * 8 + (q - 32)];
    }
    ((float4*)g_hin)[i] = v;
}

// ---------------------------------------------------------------------------
// Kernel 2: combined bias + W_hh transpose to k-major
// ---------------------------------------------------------------------------
__global__ void prep_kernel(const float* __restrict__ W_hh,
                            const float* __restrict__ b_ih,
                            const float* __restrict__ b_hh) {
    int t0 = blockIdx.x * blockDim.x + threadIdx.x;
    if (t0 < G4) g_bias[t0] = b_ih[t0] + b_hh[t0];
    int total = G4 * FDIM;
    int stride = gridDim.x * blockDim.x;
    for (int idx = t0; idx < total; idx += stride) {
        int r = idx / FDIM;
        int k = idx - r * FDIM;
        g_wt[k * G4 + r] = W_hh[idx];
    }
}

// ---------------------------------------------------------------------------
// Kernel 3: generic C[M,Nc] = h_in[M,160] @ B[Nc,160]^T + bias   (FFMA2)
//   mode 0: C = g_gall (Nc=640), bias = g_bias
//   mode 1: C = g_rout (Nc=128), bias = biasp (b_l)
// BM=BN=64, BK=16, 256 threads, 4x4 register tile as 4x2 packed pairs.
// ---------------------------------------------------------------------------
__global__ void gemm_kernel(const float* __restrict__ B,
                            const float* __restrict__ biasp,
                            int Nc, int N, int mode) {
    __shared__ float As[16][64];
    __shared__ float Bs[16][64];
    const float* A = g_hin;
    float* C = (mode == 0) ? g_gall : g_rout;

    int m0 = blockIdx.y * 64;
    int n0 = blockIdx.x * 64;
    int t  = threadIdx.x;
    int lr = t >> 2, lq = t & 3;     // load mapping: 64 rows x 4 float4
    int tx = t & 15, ty = t >> 4;    // compute mapping: 16x16 threads

    ull acc[4][2];
#pragma unroll
    for (int i = 0; i < 4; i++) { acc[i][0] = 0ull; acc[i][1] = 0ull; }

    for (int kc = 0; kc < FDIM; kc += 16) {
        float4 av = make_float4(0.f, 0.f, 0.f, 0.f);
        int am = m0 + lr;
        if (am < N) av = *(const float4*)(A + (size_t)am * FDIM + kc + lq * 4);
        As[lq * 4 + 0][lr] = av.x; As[lq * 4 + 1][lr] = av.y;
        As[lq * 4 + 2][lr] = av.z; As[lq * 4 + 3][lr] = av.w;

        float4 bv = *(const float4*)(B + (size_t)(n0 + lr) * FDIM + kc + lq * 4);
        Bs[lq * 4 + 0][lr] = bv.x; Bs[lq * 4 + 1][lr] = bv.y;
        Bs[lq * 4 + 2][lr] = bv.z; Bs[lq * 4 + 3][lr] = bv.w;
        __syncthreads();

#pragma unroll
        for (int kk = 0; kk < 16; kk++) {
            float4 a4 = *(const float4*)&As[kk][ty * 4];
            longlong2 b2 = *(const longlong2*)&Bs[kk][tx * 4];
            ull bx = (ull)b2.x, by = (ull)b2.y;
            float a[4] = {a4.x, a4.y, a4.z, a4.w};
#pragma unroll
            for (int i = 0; i < 4; i++) {
                ull a2 = dup2(a[i]);
                acc[i][0] = ffma2(a2, bx, acc[i][0]);
                acc[i][1] = ffma2(a2, by, acc[i][1]);
            }
        }
        __syncthreads();
    }

    const float* bias = (mode == 0) ? g_bias : biasp;
    float4 bb = *(const float4*)(bias + n0 + tx * 4);
#pragma unroll
    for (int i = 0; i < 4; i++) {
        int m = m0 + ty * 4 + i;
        if (m < N) {
            float2 lo = unpk(acc[i][0]);
            float2 hi = unpk(acc[i][1]);
            float4 o;
            o.x = lo.x + bb.x;
            o.y = lo.y + bb.y;
            o.z = hi.x + bb.z;
            o.w = hi.y + bb.w;
            *(float4*)(C + (size_t)m * Nc + n0 + tx * 4) = o;
        }
    }
}

// ---------------------------------------------------------------------------
// Kernel 4: persistent-tile LSTM over 16 neighbors + fused SAGE projection.
// CTA = 320 threads, 32 nodes. Thread tile: 8 nodes x 2 hidden x 4 gates
// kept as 32 packed f32x2 accumulators -> FFMA2-pipe-bound.
// h in SMEM, c in registers, W_hh streamed k-major via SMEM with reg prefetch.
// ---------------------------------------------------------------------------
__device__ __forceinline__ float sigm(float x)     { return 1.f / (1.f + __expf(-x)); }
__device__ __forceinline__ float tanhfast(float x) { return 1.f - 2.f / (1.f + __expf(2.f * x)); }

__global__ __launch_bounds__(320) void lstm_kernel(const int* __restrict__ src,
                                                   const float* __restrict__ Wl,
                                                   float* __restrict__ out, int N) {
    __shared__ float sh_h[32][168];     // padded rows, 21.5 KB
    __shared__ float sh_w[8 * 640];     // one k-chunk of W_hh^T, 20 KB

    int t  = threadIdx.x;
    int mg = t / 80;            // 0..3  -> node group (8 nodes each)
    int rg = t % 80;            // 0..79 -> hidden pair index (2 floats)
    int mbase = mg * 8;
    int node0 = blockIdx.x * 32;

    // zero-init h (pad included — harmless)
    for (int i = t; i < 32 * 168; i += 320) (&sh_h[0][0])[i] = 0.f;

    float cst[8][2];
#pragma unroll
    for (int i = 0; i < 8; i++) { cst[i][0] = 0.f; cst[i][1] = 0.f; }

    // preload W chunk 0 into registers
    float4 wbuf[4];
    {
        const float4* ws = (const float4*)g_wt;
#pragma unroll
        for (int q = 0; q < 4; q++) wbuf[q] = ws[q * 320 + t];
    }
    __syncthreads();

    for (int step = 0; step < DEG; step++) {
        // accumulator init = gathered precomputed input gates (incl. biases)
        // acc[mi][gi] holds gate block gi, hidden pair rg, for node mbase+mi
        ull acc[8][4];
#pragma unroll
        for (int mi = 0; mi < 8; mi++) {
            int nd = node0 + mbase + mi;
            int s = (nd < N) ? src[nd * DEG + step] : 0;
            const ull* gp = (const ull*)(g_gall + (size_t)s * G4);
#pragma unroll
            for (int gi = 0; gi < 4; gi++) acc[mi][gi] = gp[gi * 80 + rg];
        }

        // recurrent GEMM: acc += h @ W_hh^T   (k-chunks of 8, reg-staged prefetch)
        for (int kc = 0; kc < FDIM; kc += 8) {
            __syncthreads();                       // prior chunk reads done
            float4* wd = (float4*)sh_w;
#pragma unroll
            for (int q = 0; q < 4; q++) wd[q * 320 + t] = wbuf[q];
            __syncthreads();
            {   // prefetch next chunk (chunk 0 of next step when wrapping)
                int nk = (kc + 8 < FDIM) ? kc + 8 : 0;
                const float4* ws = (const float4*)(g_wt + nk * G4);
#pragma unroll
                for (int q = 0; q < 4; q++) wbuf[q] = ws[q * 320 + t];
            }
#pragma unroll
            for (int kk = 0; kk < 8; kk++) {
                ull b[4];
#pragma unroll
                for (int gi = 0; gi < 4; gi++)
                    b[gi] = *(const ull*)&sh_w[kk * 640 + gi * 160 + rg * 2];
#pragma unroll
                for (int mi = 0; mi < 8; mi++) {
                    ull a2 = dup2(sh_h[mbase + mi][kc + kk]);   // smem broadcast
#pragma unroll
                    for (int gi = 0; gi < 4; gi++)
                        acc[mi][gi] = ffma2(a2, b[gi], acc[mi][gi]);
                }
            }
        }
        __syncthreads();   // all sh_h reads done before update

        // elementwise LSTM cell update; write new h pair to SMEM
#pragma unroll
        for (int mi = 0; mi < 8; mi++) {
            float2 ig = unpk(acc[mi][0]);
            float2 fg = unpk(acc[mi][1]);
            float2 gg = unpk(acc[mi][2]);
            float2 og = unpk(acc[mi][3]);
            float c0 = sigm(fg.x) * cst[mi][0] + sigm(ig.x) * tanhfast(gg.x);
            float c1 = sigm(fg.y) * cst[mi][1] + sigm(ig.y) * tanhfast(gg.y);
            cst[mi][0] = c0; cst[mi][1] = c1;
            float2 hn;
            hn.x = sigm(og.x) * tanhfast(c0);
            hn.y = sigm(og.y) * tanhfast(c1);
            *(float2*)&sh_h[mbase + mi][rg * 2] = hn;
        }
        __syncthreads();
    }

    // fused SAGE projection: out = relu(h_last @ W_l^T + (h_in @ W_r^T + b_l))
    if (rg < 64) {
        int c0 = rg * 2;            // output columns c0, c0+1
        float s[8][2];
#pragma unroll
        for (int mi = 0; mi < 8; mi++) { s[mi][0] = 0.f; s[mi][1] = 0.f; }
#pragma unroll 4
        for (int k = 0; k < FDIM; k += 4) {
            float4 w0 = *(const float4*)(Wl + (size_t)(c0 + 0) * FDIM + k);
            float4 w1 = *(const float4*)(Wl + (size_t)(c0 + 1) * FDIM + k);
#pragma unroll
            for (int mi = 0; mi < 8; mi++) {
                float4 hv = *(const float4*)&sh_h[mbase + mi][k];
                s[mi][0] += hv.x * w0.x + hv.y * w0.y + hv.z * w0.z + hv.w * w0.w;
                s[mi][1] += hv.x * w1.x + hv.y * w1.y + hv.z * w1.z + hv.w * w1.w;
            }
        }
#pragma unroll
        for (int mi = 0; mi < 8; mi++) {
            int nd = node0 + mbase + mi;
            if (nd >= N) continue;
            float2 rv = *(const float2*)(g_rout + (size_t)nd * OUTC + c0);
            float2 o;
            o.x = fmaxf(s[mi][0] + rv.x, 0.f);
            o.y = fmaxf(s[mi][1] + rv.y, 0.f);
            *(float2*)(out + (size_t)nd * OUTC + c0) = o;
        }
    }
}

// ---------------------------------------------------------------------------
// Launcher (graph-capturable: kernel launches only, stream-ordered deps)
// ---------------------------------------------------------------------------
extern "C" void kernel_launch(void* const* d_in, const int* in_sizes, int n_in,
                              void* d_out, int out_size) {
    const float* x     = (const float*)d_in[0];
    const int*   types = (const int*)d_in[1];
    const int*   eidx  = (const int*)d_in[2];   // [2, E]: first E entries = src
    const float* emb   = (const float*)d_in[3];
    const float* W_ih  = (const float*)d_in[4];
    const float* W_hh  = (const float*)d_in[5];
    const float* b_ih  = (const float*)d_in[6];
    const float* b_hh  = (const float*)d_in[7];
    const float* W_l   = (const float*)d_in[8];
    const float* b_l   = (const float*)d_in[9];
    const float* W_r   = (const float*)d_in[10];
    float* out = (float*)d_out;

    int N = in_sizes[1];                 // = 50000
    const int* srcp = eidx;              // src row of edge_index

    concat_kernel<<<(N * 40 + 255) / 256, 256>>>(x, types, emb, N);
    prep_kernel<<<160, 256>>>(W_hh, b_ih, b_hh);

    dim3 g1(G4 / 64, (N + 63) / 64);
    gemm_kernel<<<g1, 256>>>(W_ih, nullptr, G4, N, 0);
    dim3 g2(OUTC / 64, (N + 63) / 64);
    gemm_kernel<<<g2, 256>>>(W_r, b_l, OUTC, N, 1);

    lstm_kernel<<<(N + 31) / 32, 320>>>(srcp, W_l, out, N);
}

// round 9
// speedup vs baseline: 1.4534x; 1.2339x over previous
#include <cuda_runtime.h>
#include <math.h>

// Problem constants (fixed by the dataset)
#define NN    50000
#define FDIM  160
#define KD    160
#define G4    640
#define DEG   16
#define OUTC  128
#define HS    16              // hidden units per col-group CTA
#define CG    64              // cols per CTA (HS hidden x 4 gates)
#define NCG   10              // col groups (160 / HS)
#define MT    64              // M tile (nodes per CTA)
#define MTILES ((NN + MT - 1) / MT)

typedef unsigned long long ull;
typedef unsigned int uint;

// Scratch (device globals — no runtime allocation allowed)
__device__ float g_hin [(size_t)NN * FDIM];   // concat(x, emb)
__device__ float g_gall[(size_t)NN * G4];     // permuted (hidden*4+gate) input gates
__device__ float g_rout[(size_t)NN * OUTC];   // h_in@W_r^T + b_l
__device__ float g_h0  [(size_t)NN * FDIM];   // h ping
__device__ float g_h1  [(size_t)NN * FDIM];   // h pong
__device__ float g_c   [(size_t)NN * FDIM];   // cell state

// ---------------------------------------------------------------------------
// helpers
// ---------------------------------------------------------------------------
__device__ __forceinline__ uint tf32c(float x) {
    uint r; asm("cvt.rna.tf32.f32 %0, %1;" : "=r"(r) : "f"(x)); return r;
}
__device__ __forceinline__ void mma8(float& d0, float& d1, float& d2, float& d3,
                                     uint a0, uint a1, uint a2, uint a3,
                                     uint b0, uint b1) {
    asm volatile("mma.sync.aligned.m16n8k8.row.col.f32.tf32.tf32.f32 "
                 "{%0,%1,%2,%3},{%4,%5,%6,%7},{%8,%9},{%0,%1,%2,%3};"
                 : "+f"(d0), "+f"(d1), "+f"(d2), "+f"(d3)
                 : "r"(a0), "r"(a1), "r"(a2), "r"(a3), "r"(b0), "r"(b1));
}
__device__ __forceinline__ ull ffma2(ull a, ull b, ull c) {
    ull d; asm("fma.rn.f32x2 %0, %1, %2, %3;" : "=l"(d) : "l"(a), "l"(b), "l"(c));
    return d;
}
__device__ __forceinline__ ull dup2(float x) {
    ull r; asm("mov.b64 %0, {%1, %1};" : "=l"(r) : "f"(x)); return r;
}
__device__ __forceinline__ float2 unpk(ull v) {
    float2 r; asm("mov.b64 {%0, %1}, %2;" : "=f"(r.x), "=f"(r.y) : "l"(v)); return r;
}
__device__ __forceinline__ float sigm(float x)     { return 1.f / (1.f + __expf(-x)); }
__device__ __forceinline__ float tanhfast(float x) { return 1.f - 2.f / (1.f + __expf(2.f * x)); }

// Dynamic SMEM layout (floats)
#define W_OFF 0                 // [64][164]  = 10496 floats
#define G_OFF 10496             // [64][68]   = 4352
#define C_OFF 14848             // [64][20]   = 1280
#define H_OFF 16128             // [64][20]   = 1280
#define STEP_SMEM (17408 * 4)   // 69632 B
#define PRE_SMEM  (14848 * 4)   // 59392 B

// ---------------------------------------------------------------------------
// Kernel 1: h_in = concat(x, emb_table[node_type_ids])
// ---------------------------------------------------------------------------
__global__ void concat_kernel(const float* __restrict__ x,
                              const int* __restrict__ types,
                              const float* __restrict__ emb, int N) {
    int i = blockIdx.x * blockDim.x + threadIdx.x;   // float4 index over N*40
    if (i >= N * 40) return;
    int n = i / 40;
    int q = i - n * 40;
    float4 v;
    if (q < 32) {
        v = ((const float4*)x)[n * 32 + q];
    } else {
        int tp = types[n];
        v = ((const float4*)emb)[tp * 8 + (q - 32)];
    }
    ((float4*)g_hin)[i] = v;
}

// ---------------------------------------------------------------------------
// Kernel 2 (tensor-core): g_gall[n][c] = g_hin[n]@W_ih[row(c)] + b_ih + b_hh
// permuted columns: c = hidden_local*4 + gate ; W row = gate*160 + hidden.
// CTA: 256 thr, 8 warps (4 m-warps x 2 n-warps). M=64, Ncols=64, K=160.
// ---------------------------------------------------------------------------
__global__ __launch_bounds__(256) void tc_pre(const float* __restrict__ Wih,
                                              const float* __restrict__ bih,
                                              const float* __restrict__ bhh, int N) {
    extern __shared__ float sm[];
    uint*  Wu  = (uint*)sm;          // [64][164] tf32 bits
    float* Gsh = sm + G_OFF;         // [64][68]
    __shared__ float bsh[CG];

    int t = threadIdx.x, lane = t & 31, warp = t >> 5;
    int wm = warp & 3, wn = warp >> 2;
    int cg = blockIdx.x, mt = blockIdx.y;
    int node0 = mt * MT;

    if (t < CG) {
        int wrow = (t & 3) * KD + cg * HS + (t >> 2);
        bsh[t] = bih[wrow] + bhh[wrow];
    }
    for (int idx = t; idx < CG * 40; idx += 256) {
        int row = idx / 40, f4 = idx % 40;
        int wrow = (row & 3) * KD + cg * HS + (row >> 2);
        float4 v = *(const float4*)(Wih + (size_t)wrow * KD + f4 * 4);
        uint* wp = Wu + row * 164 + f4 * 4;
        wp[0] = tf32c(v.x); wp[1] = tf32c(v.y); wp[2] = tf32c(v.z); wp[3] = tf32c(v.w);
    }
    __syncthreads();

    float d[4][4];
#pragma unroll
    for (int i = 0; i < 4; i++)
#pragma unroll
        for (int j = 0; j < 4; j++) d[i][j] = 0.f;

    int r0 = node0 + wm * 16 + (lane >> 2);
    int r1 = r0 + 8;
    if (r0 >= N) r0 = N - 1;
    if (r1 >= N) r1 = N - 1;
    const float* Ap0 = g_hin + (size_t)r0 * KD + (lane & 3);
    const float* Ap1 = g_hin + (size_t)r1 * KD + (lane & 3);
    uint a0 = tf32c(Ap0[0]), a2 = tf32c(Ap0[4]);
    uint a1 = tf32c(Ap1[0]), a3 = tf32c(Ap1[4]);
    const uint* Wb = Wu + (size_t)(wn * 32 + (lane >> 2)) * 164 + (lane & 3);

    for (int ks = 0; ks < 20; ks++) {
        int k = ks * 8;
        uint n0 = 0, n1 = 0, n2 = 0, n3 = 0;
        if (ks < 19) {
            n0 = tf32c(Ap0[k + 8]); n2 = tf32c(Ap0[k + 12]);
            n1 = tf32c(Ap1[k + 8]); n3 = tf32c(Ap1[k + 12]);
        }
#pragma unroll
        for (int t8 = 0; t8 < 4; t8++) {
            const uint* wp = Wb + t8 * 8 * 164 + k;
            mma8(d[t8][0], d[t8][1], d[t8][2], d[t8][3],
                 a0, a1, a2, a3, wp[0], wp[4]);
        }
        a0 = n0; a1 = n1; a2 = n2; a3 = n3;
    }

#pragma unroll
    for (int t8 = 0; t8 < 4; t8++) {
        int cb = wn * 32 + t8 * 8 + (lane & 3) * 2;
        int rr = wm * 16 + (lane >> 2);
        Gsh[rr * 68 + cb]           = d[t8][0] + bsh[cb];
        Gsh[rr * 68 + cb + 1]       = d[t8][1] + bsh[cb + 1];
        Gsh[(rr + 8) * 68 + cb]     = d[t8][2] + bsh[cb];
        Gsh[(rr + 8) * 68 + cb + 1] = d[t8][3] + bsh[cb + 1];
    }
    __syncthreads();
    {
        int i = t >> 2, q = t & 3;
        int nd = node0 + i;
        if (nd < N) {
            float* op = g_gall + (size_t)nd * G4 + cg * CG + q * 16;
            const float* sp = Gsh + i * 68 + q * 16;
#pragma unroll
            for (int j = 0; j < 4; j++)
                *(float4*)(op + j * 4) = *(const float4*)(sp + j * 4);
        }
    }
}

// ---------------------------------------------------------------------------
// Kernel 3 (tensor-core): one LSTM step.
// gates = gather(g_gall, src) + h_prev @ W_hh^T ; fused cell update epilogue.
// Same tile shape as tc_pre. h ping-pongs between g_h0/g_h1 by step parity.
// ---------------------------------------------------------------------------
__global__ __launch_bounds__(256) void tc_step(const float* __restrict__ Whh,
                                               const int* __restrict__ src,
                                               int step, int first, int N) {
    extern __shared__ float sm[];
    uint*  Wu  = (uint*)sm;          // [64][164]
    float* Gsh = sm + G_OFF;         // [64][68]  gathered gates
    float* Csh = sm + C_OFF;         // [64][20]  cell state slice
    float* Hsh = sm + H_OFF;         // [64][20]  new h slice

    const float* hr = (step & 1) ? g_h1 : g_h0;
    float*       hw = (step & 1) ? g_h0 : g_h1;

    int t = threadIdx.x, lane = t & 31, warp = t >> 5;
    int wm = warp & 3, wn = warp >> 2;
    int cg = blockIdx.x, mt = blockIdx.y;
    int node0 = mt * MT;

    // stage gather (coalesced 256B per node) + cell-state slice
    {
        int i = t >> 2, q = t & 3;
        int nd = node0 + i;
        int s = (nd < N) ? src[nd * DEG + step] : 0;
        const float* gp = g_gall + (size_t)s * G4 + cg * CG + q * 16;
        float* dp = Gsh + i * 68 + q * 16;
#pragma unroll
        for (int j = 0; j < 4; j++)
            *(float4*)(dp + j * 4) = *(const float4*)(gp + j * 4);
        if (!first) {
            int rn = (nd < N) ? nd : 0;
            *(float4*)(Csh + i * 20 + q * 4) =
                *(const float4*)(g_c + (size_t)rn * KD + cg * HS + q * 4);
        }
    }
    if (!first) {
        for (int idx = t; idx < CG * 40; idx += 256) {
            int row = idx / 40, f4 = idx % 40;
            int wrow = (row & 3) * KD + cg * HS + (row >> 2);
            float4 v = *(const float4*)(Whh + (size_t)wrow * KD + f4 * 4);
            uint* wp = Wu + row * 164 + f4 * 4;
            wp[0] = tf32c(v.x); wp[1] = tf32c(v.y); wp[2] = tf32c(v.z); wp[3] = tf32c(v.w);
        }
    }
    __syncthreads();

    float d[4][4];
#pragma unroll
    for (int i = 0; i < 4; i++)
#pragma unroll
        for (int j = 0; j < 4; j++) d[i][j] = 0.f;

    if (!first) {
        int r0 = node0 + wm * 16 + (lane >> 2);
        int r1 = r0 + 8;
        if (r0 >= N) r0 = N - 1;
        if (r1 >= N) r1 = N - 1;
        const float* Ap0 = hr + (size_t)r0 * KD + (lane & 3);
        const float* Ap1 = hr + (size_t)r1 * KD + (lane & 3);
        uint a0 = tf32c(Ap0[0]), a2 = tf32c(Ap0[4]);
        uint a1 = tf32c(Ap1[0]), a3 = tf32c(Ap1[4]);
        const uint* Wb = Wu + (size_t)(wn * 32 + (lane >> 2)) * 164 + (lane & 3);

        for (int ks = 0; ks < 20; ks++) {
            int k = ks * 8;
            uint n0 = 0, n1 = 0, n2 = 0, n3 = 0;
            if (ks < 19) {
                n0 = tf32c(Ap0[k + 8]); n2 = tf32c(Ap0[k + 12]);
                n1 = tf32c(Ap1[k + 8]); n3 = tf32c(Ap1[k + 12]);
            }
#pragma unroll
            for (int t8 = 0; t8 < 4; t8++) {
                const uint* wp = Wb + t8 * 8 * 164 + k;
                mma8(d[t8][0], d[t8][1], d[t8][2], d[t8][3],
                     a0, a1, a2, a3, wp[0], wp[4]);
            }
            a0 = n0; a1 = n1; a2 = n2; a3 = n3;
        }
    }

    // epilogue: exchange so each thread owns (i,f,g,o) of one (node,hidden)
    int pr = lane & 1;
    int nloc = wm * 16 + (lane >> 2) + pr * 8;
#pragma unroll
    for (int t8 = 0; t8 < 4; t8++) {
        float v0 = pr ? d[t8][0] : d[t8][2];
        float v1 = pr ? d[t8][1] : d[t8][3];
        v0 = __shfl_xor_sync(0xffffffffu, v0, 1);
        v1 = __shfl_xor_sync(0xffffffffu, v1, 1);
        float gi, gf, gg, go;
        if (pr) { gi = v0;       gf = v1;       gg = d[t8][2]; go = d[t8][3]; }
        else    { gi = d[t8][0]; gf = d[t8][1]; gg = v0;       go = v1;       }
        int hl = wn * 8 + t8 * 2 + ((lane >> 1) & 1);
        float4 gv = *(const float4*)(Gsh + nloc * 68 + hl * 4);
        gi += gv.x; gf += gv.y; gg += gv.z; go += gv.w;
        float cold = first ? 0.f : Csh[nloc * 20 + hl];
        float cn = sigm(gf) * cold + sigm(gi) * tanhfast(gg);
        float hn = sigm(go) * tanhfast(cn);
        Csh[nloc * 20 + hl] = cn;
        Hsh[nloc * 20 + hl] = hn;
    }
    __syncthreads();

    // coalesced writeout of h / c slices
    {
        int i = t >> 2, q = t & 3;
        int nd = node0 + i;
        if (nd < N) {
            *(float4*)(hw  + (size_t)nd * KD + cg * HS + q * 4) =
                *(const float4*)(Hsh + i * 20 + q * 4);
            *(float4*)(g_c + (size_t)nd * KD + cg * HS + q * 4) =
                *(const float4*)(Csh + i * 20 + q * 4);
        }
    }
}

// ---------------------------------------------------------------------------
// Kernel 4: FFMA2 GEMM, Nc=128.
//   mode 1: g_rout = g_hin @ W_r^T + b_l
//   mode 2: out    = relu(g_h0 @ W_l^T + g_rout)
// ---------------------------------------------------------------------------
__global__ void gemm_kernel(const float* __restrict__ B,
                            const float* __restrict__ biasp,
                            float* __restrict__ Cext, int N, int mode) {
    __shared__ float As[16][64];
    __shared__ float Bs[16][64];
    const float* A = (mode == 1) ? g_hin : g_h0;
    float* C = (mode == 1) ? g_rout : Cext;

    int m0 = blockIdx.y * 64;
    int n0 = blockIdx.x * 64;
    int t  = threadIdx.x;
    int lr = t >> 2, lq = t & 3;
    int tx = t & 15, ty = t >> 4;

    ull acc[4][2];
#pragma unroll
    for (int i = 0; i < 4; i++) { acc[i][0] = 0ull; acc[i][1] = 0ull; }

    for (int kc = 0; kc < FDIM; kc += 16) {
        float4 av = make_float4(0.f, 0.f, 0.f, 0.f);
        int am = m0 + lr;
        if (am < N) av = *(const float4*)(A + (size_t)am * FDIM + kc + lq * 4);
        As[lq * 4 + 0][lr] = av.x; As[lq * 4 + 1][lr] = av.y;
        As[lq * 4 + 2][lr] = av.z; As[lq * 4 + 3][lr] = av.w;

        float4 bv = *(const float4*)(B + (size_t)(n0 + lr) * FDIM + kc + lq * 4);
        Bs[lq * 4 + 0][lr] = bv.x; Bs[lq * 4 + 1][lr] = bv.y;
        Bs[lq * 4 + 2][lr] = bv.z; Bs[lq * 4 + 3][lr] = bv.w;
        __syncthreads();

#pragma unroll
        for (int kk = 0; kk < 16; kk++) {
            float4 a4 = *(const float4*)&As[kk][ty * 4];
            longlong2 b2 = *(const longlong2*)&Bs[kk][tx * 4];
            ull bx = (ull)b2.x, by = (ull)b2.y;
            float a[4] = {a4.x, a4.y, a4.z, a4.w};
#pragma unroll
            for (int i = 0; i < 4; i++) {
                ull a2 = dup2(a[i]);
                acc[i][0] = ffma2(a2, bx, acc[i][0]);
                acc[i][1] = ffma2(a2, by, acc[i][1]);
            }
        }
        __syncthreads();
    }

#pragma unroll
    for (int i = 0; i < 4; i++) {
        int m = m0 + ty * 4 + i;
        if (m < N) {
            float2 lo = unpk(acc[i][0]);
            float2 hi = unpk(acc[i][1]);
            float4 o;
            if (mode == 1) {
                float4 bb = *(const float4*)(biasp + n0 + tx * 4);
                o.x = lo.x + bb.x; o.y = lo.y + bb.y;
                o.z = hi.x + bb.z; o.w = hi.y + bb.w;
            } else {
                float4 rv = *(const float4*)(g_rout + (size_t)m * OUTC + n0 + tx * 4);
                o.x = fmaxf(lo.x + rv.x, 0.f);
                o.y = fmaxf(lo.y + rv.y, 0.f);
                o.z = fmaxf(hi.x + rv.z, 0.f);
                o.w = fmaxf(hi.y + rv.w, 0.f);
            }
            *(float4*)(C + (size_t)m * OUTC + n0 + tx * 4) = o;
        }
    }
}

// ---------------------------------------------------------------------------
// Launcher (graph-capturable: kernel launches only)
// ---------------------------------------------------------------------------
extern "C" void kernel_launch(void* const* d_in, const int* in_sizes, int n_in,
                              void* d_out, int out_size) {
    const float* x     = (const float*)d_in[0];
    const int*   types = (const int*)d_in[1];
    const int*   eidx  = (const int*)d_in[2];   // [2, E]: first E entries = src
    const float* emb   = (const float*)d_in[3];
    const float* W_ih  = (const float*)d_in[4];
    const float* W_hh  = (const float*)d_in[5];
    const float* b_ih  = (const float*)d_in[6];
    const float* b_hh  = (const float*)d_in[7];
    const float* W_l   = (const float*)d_in[8];
    const float* b_l   = (const float*)d_in[9];
    const float* W_r   = (const float*)d_in[10];
    float* out = (float*)d_out;

    int N = in_sizes[1];                 // = 50000
    const int* srcp = eidx;

    cudaFuncSetAttribute((const void*)tc_pre,
                         cudaFuncAttributeMaxDynamicSharedMemorySize, PRE_SMEM);
    cudaFuncSetAttribute((const void*)tc_step,
                         cudaFuncAttributeMaxDynamicSharedMemorySize, STEP_SMEM);

    concat_kernel<<<(N * 40 + 255) / 256, 256>>>(x, types, emb, N);

    dim3 gtc(NCG, (N + MT - 1) / MT);
    tc_pre<<<gtc, 256, PRE_SMEM>>>(W_ih, b_ih, b_hh, N);

    dim3 g2(2, (N + 63) / 64);
    gemm_kernel<<<g2, 256>>>(W_r, b_l, nullptr, N, 1);

    for (int s = 0; s < DEG; s++)
        tc_step<<<gtc, 256, STEP_SMEM>>>(W_hh, srcp, s, (s == 0) ? 1 : 0, N);

    gemm_kernel<<<g2, 256>>>(W_l, nullptr, out, N, 2);
}